// round 12
// baseline (speedup 1.0000x reference)
#include <cuda_runtime.h>
#include <cuda_bf16.h>
#include <math.h>
#include <stdint.h>

// Problem constants
#define B_  2
#define T_  2048
#define C_  1536
#define H_  16
#define D_  96
#define C3_ (3 * C_)      // 4608
#define BT_ (B_ * T_)     // 4096
#define BH_ (B_ * H_)     // 32

// fp32 scratch
__device__ float g_qkv[(size_t)BT_ * C3_];

// bf16 hi/lo split scratch for GEMMs
__device__ __nv_bfloat16 g_xh [(size_t)BT_  * C_];
__device__ __nv_bfloat16 g_xl [(size_t)BT_  * C_];
__device__ __nv_bfloat16 g_wqh[(size_t)C3_  * C_];
__device__ __nv_bfloat16 g_wql[(size_t)C3_  * C_];
__device__ __nv_bfloat16 g_ath[(size_t)BT_  * C_];
__device__ __nv_bfloat16 g_atl[(size_t)BT_  * C_];
__device__ __nv_bfloat16 g_woh[(size_t)C_   * C_];
__device__ __nv_bfloat16 g_wol[(size_t)C_   * C_];

// bf16 hi/lo q/k/v for attention, layout [bh][t][d]
__device__ __nv_bfloat16 g_qh[(size_t)BH_ * T_ * D_];
__device__ __nv_bfloat16 g_ql[(size_t)BH_ * T_ * D_];
__device__ __nv_bfloat16 g_kh[(size_t)BH_ * T_ * D_];
__device__ __nv_bfloat16 g_kl[(size_t)BH_ * T_ * D_];
__device__ __nv_bfloat16 g_vh[(size_t)BH_ * T_ * D_];
__device__ __nv_bfloat16 g_vl[(size_t)BH_ * T_ * D_];

// ---------------------------------------------------------------------------
// helpers
// ---------------------------------------------------------------------------
#define MMA_BF16(d, a, b)                                                     \
    asm volatile(                                                             \
        "mma.sync.aligned.m16n8k16.row.col.f32.bf16.bf16.f32 "                \
        "{%0,%1,%2,%3}, {%4,%5,%6,%7}, {%8,%9}, {%0,%1,%2,%3};"               \
        : "+f"((d)[0]), "+f"((d)[1]), "+f"((d)[2]), "+f"((d)[3])              \
        : "r"((a)[0]), "r"((a)[1]), "r"((a)[2]), "r"((a)[3]),                 \
          "r"((b)[0]), "r"((b)[1]))

#define LDSM_X4(r, a)                                                         \
    asm volatile("ldmatrix.sync.aligned.m8n8.x4.shared.b16 {%0,%1,%2,%3}, [%4];" \
        : "=r"((r)[0]), "=r"((r)[1]), "=r"((r)[2]), "=r"((r)[3]) : "r"(a))

#define LDSM_X4_T(r, a)                                                       \
    asm volatile("ldmatrix.sync.aligned.m8n8.x4.trans.shared.b16 {%0,%1,%2,%3}, [%4];" \
        : "=r"((r)[0]), "=r"((r)[1]), "=r"((r)[2]), "=r"((r)[3]) : "r"(a))

#define CP16(dst, src)                                                        \
    asm volatile("cp.async.cg.shared.global [%0], [%1], 16;"                  \
        :: "r"(dst), "l"(src))
#define CP_COMMIT() asm volatile("cp.async.commit_group;")
#define CP_WAIT(n)  asm volatile("cp.async.wait_group %0;" :: "n"(n))

// ---------------------------------------------------------------------------
// fp32 -> (bf16 hi, bf16 lo) split.  n must be divisible by 4.
// ---------------------------------------------------------------------------
__global__ __launch_bounds__(256)
void split_kernel(const float* __restrict__ in,
                  __nv_bfloat16* __restrict__ hi,
                  __nv_bfloat16* __restrict__ lo, int n) {
    int i = (blockIdx.x * 256 + threadIdx.x) * 4;
    if (i >= n) return;
    float4 v = *reinterpret_cast<const float4*>(in + i);
    __nv_bfloat16 h0 = __float2bfloat16(v.x);
    __nv_bfloat16 h1 = __float2bfloat16(v.y);
    __nv_bfloat16 h2 = __float2bfloat16(v.z);
    __nv_bfloat16 h3 = __float2bfloat16(v.w);
    __nv_bfloat16 l0 = __float2bfloat16(v.x - __bfloat162float(h0));
    __nv_bfloat16 l1 = __float2bfloat16(v.y - __bfloat162float(h1));
    __nv_bfloat16 l2 = __float2bfloat16(v.z - __bfloat162float(h2));
    __nv_bfloat16 l3 = __float2bfloat16(v.w - __bfloat162float(h3));
    __nv_bfloat162* hp = reinterpret_cast<__nv_bfloat162*>(hi + i);
    __nv_bfloat162* lp = reinterpret_cast<__nv_bfloat162*>(lo + i);
    hp[0] = __nv_bfloat162(h0, h1);
    hp[1] = __nv_bfloat162(h2, h3);
    lp[0] = __nv_bfloat162(l0, l1);
    lp[1] = __nv_bfloat162(l2, l3);
}

// ---------------------------------------------------------------------------
// Tensor-core GEMM (NT) with bf16 hi/lo split, cp.async double buffer,
// ldmatrix operand fetch, k-tile 32, SA=40, single barrier per k-iter.
// (Round-10 measured-best configuration, exactly.)
// ---------------------------------------------------------------------------
#define SA 40
#define ARR_B   (128 * SA * 2)
#define STAGE_B (4 * ARR_B)
#define GSM_BYTES (2 * STAGE_B)

__global__ __launch_bounds__(256)
void bmma_nt(const __nv_bfloat16* __restrict__ Ah,
             const __nv_bfloat16* __restrict__ Al,
             const __nv_bfloat16* __restrict__ Bh,
             const __nv_bfloat16* __restrict__ Bl,
             float* __restrict__ Cm, int M, int N, int K) {
    extern __shared__ __nv_bfloat16 gsm[];
    const uint32_t smemU = (uint32_t)__cvta_generic_to_shared(gsm);

    const int tid  = threadIdx.x;
    const int m0   = blockIdx.y * 128;
    const int n0   = blockIdx.x * 128;
    const int lr   = tid >> 1;
    const int lh   = tid & 1;
    const int warp = tid >> 5;
    const int lane = tid & 31;
    const int wm   = (warp & 1) * 64;
    const int wn   = (warp >> 1) * 32;
    const int g    = lane >> 2;
    const int t    = lane & 3;
    const int tile = lane >> 3;

    const __nv_bfloat16* aph = Ah + (size_t)(m0 + lr) * K + lh * 16;
    const __nv_bfloat16* apl = Al + (size_t)(m0 + lr) * K + lh * 16;
    const __nv_bfloat16* bph = Bh + (size_t)(n0 + lr) * K + lh * 16;
    const __nv_bfloat16* bpl = Bl + (size_t)(n0 + lr) * K + lh * 16;

    const uint32_t dOff = (uint32_t)(lr * SA + lh * 16) * 2;
    const uint32_t aByte = (uint32_t)((wm + (lane & 15)) * SA + (lane >> 4) * 8) * 2;
    const uint32_t bByte = (uint32_t)((wn + (tile >> 1) * 8 + (lane & 7)) * SA +
                                      (tile & 1) * 8) * 2;

    float acc[4][4][4];
    #pragma unroll
    for (int i = 0; i < 4; i++)
        #pragma unroll
        for (int j = 0; j < 4; j++)
            #pragma unroll
            for (int r = 0; r < 4; r++) acc[i][j][r] = 0.f;

    const int nkt = K / 32;

    auto issue_stage = [&](int kt) {
        const int ko = kt * 32;
        const uint32_t sb = smemU + (kt & 1) * STAGE_B + dOff;
        CP16(sb,                  aph + ko);
        CP16(sb + 16,             aph + ko + 8);
        CP16(sb + ARR_B,          apl + ko);
        CP16(sb + ARR_B + 16,     apl + ko + 8);
        CP16(sb + 2 * ARR_B,      bph + ko);
        CP16(sb + 2 * ARR_B + 16, bph + ko + 8);
        CP16(sb + 3 * ARR_B,      bpl + ko);
        CP16(sb + 3 * ARR_B + 16, bpl + ko + 8);
        CP_COMMIT();
    };

    issue_stage(0);

    for (int kt = 0; kt < nkt; kt++) {
        CP_WAIT(0);          // stage kt landed (only group in flight per thread)
        __syncthreads();     // everyone finished reading stage kt-1
        if (kt + 1 < nkt) issue_stage(kt + 1);  // other buffer; overlaps MMAs

        const uint32_t stage = smemU + (kt & 1) * STAGE_B;

        #pragma unroll
        for (int kk = 0; kk < 32; kk += 16) {
            uint32_t ah[4][4], al[4][4];
            #pragma unroll
            for (int mt = 0; mt < 4; mt++) {
                const uint32_t aa = stage + aByte + mt * (16 * SA * 2) + kk * 2;
                LDSM_X4(ah[mt], aa);
                LDSM_X4(al[mt], aa + ARR_B);
            }
            uint32_t bhf[2][4], blf[2][4];
            #pragma unroll
            for (int np = 0; np < 2; np++) {
                const uint32_t ba = stage + 2 * ARR_B + bByte + np * (16 * SA * 2) + kk * 2;
                LDSM_X4(bhf[np], ba);
                LDSM_X4(blf[np], ba + ARR_B);
            }
            #pragma unroll
            for (int mt = 0; mt < 4; mt++)
                #pragma unroll
                for (int nt = 0; nt < 4; nt++) {
                    const uint32_t* bhp = &bhf[nt >> 1][(nt & 1) * 2];
                    const uint32_t* blp = &blf[nt >> 1][(nt & 1) * 2];
                    MMA_BF16(acc[mt][nt], ah[mt], bhp);
                    MMA_BF16(acc[mt][nt], ah[mt], blp);
                    MMA_BF16(acc[mt][nt], al[mt], bhp);
                }
        }
    }

    #pragma unroll
    for (int mt = 0; mt < 4; mt++)
        #pragma unroll
        for (int nt = 0; nt < 4; nt++) {
            const int row = m0 + wm + mt * 16 + g;
            const int col = n0 + wn + nt * 8 + t * 2;
            float2 v01 = make_float2(acc[mt][nt][0], acc[mt][nt][1]);
            float2 v23 = make_float2(acc[mt][nt][2], acc[mt][nt][3]);
            *reinterpret_cast<float2*>(&Cm[(size_t)row * N + col])       = v01;
            *reinterpret_cast<float2*>(&Cm[(size_t)(row + 8) * N + col]) = v23;
        }
}

// ---------------------------------------------------------------------------
// QK RMS-norm + conditional 3D RoPE + transpose to [bh][t][d] as bf16 hi/lo.
// One block per (b,t,h), 96 threads.  __sincosf fast path.
// ---------------------------------------------------------------------------
__global__ __launch_bounds__(96)
void norm_rope_kernel(const float* __restrict__ coords,
                      const int*   __restrict__ token_type,
                      const float* __restrict__ q_scale,
                      const float* __restrict__ k_scale) {
    const int idx = blockIdx.x;
    const int h = idx & (H_ - 1);
    const int t = (idx >> 4) & (T_ - 1);
    const int b = idx >> 15;
    const int d = threadIdx.x;

    const size_t rowoff = (size_t)(b * T_ + t) * C3_;
    const float qv = g_qkv[rowoff +          h * D_ + d];
    const float kv = g_qkv[rowoff + C_     + h * D_ + d];
    const float vv = g_qkv[rowoff + 2 * C_ + h * D_ + d];

    __shared__ float red[8];
    float sq = qv * qv, sk = kv * kv;
    #pragma unroll
    for (int off = 16; off > 0; off >>= 1) {
        sq += __shfl_down_sync(0xffffffffu, sq, off);
        sk += __shfl_down_sync(0xffffffffu, sk, off);
    }
    const int w = d >> 5, lane = d & 31;
    if (lane == 0) { red[w] = sq; red[4 + w] = sk; }
    __syncthreads();
    const float ssq = red[0] + red[1] + red[2];
    const float ssk = red[4] + red[5] + red[6];

    const float qn = qv * rsqrtf(ssq * (1.0f / D_) + 1e-6f) * q_scale[d];
    const float kn = kv * rsqrtf(ssk * (1.0f / D_) + 1e-6f) * k_scale[d];

    __shared__ float shq[D_], shk[D_];
    shq[d] = qn;
    shk[d] = kn;
    const int tt = token_type[b * T_ + t];
    __syncthreads();

    float qo = qn, ko = kn;
    if (tt > 0) {
        const int a = d / 32;
        const int r = d - a * 32;
        const int j = (r < 16) ? r : r - 16;
        const float coord = coords[(size_t)(b * T_ + t) * 3 + a];
        const float inv_freq = __expf(-0.57564627324851142f * (float)j);
        const float ang = coord * inv_freq;
        float s, c;
        __sincosf(ang, &s, &c);
        if (r < 16) {
            qo = qn * c - shq[d + 16] * s;
            ko = kn * c - shk[d + 16] * s;
        } else {
            qo = shq[d - 16] * s + qn * c;
            ko = shk[d - 16] * s + kn * c;
        }
    }

    const size_t hto = ((size_t)(b * H_ + h) * T_ + t) * D_ + d;
    const float qs = qo * 0.10206207261596575f;
    __nv_bfloat16 qh = __float2bfloat16(qs);
    __nv_bfloat16 kh = __float2bfloat16(ko);
    __nv_bfloat16 vh = __float2bfloat16(vv);
    g_qh[hto] = qh;
    g_ql[hto] = __float2bfloat16(qs - __bfloat162float(qh));
    g_kh[hto] = kh;
    g_kl[hto] = __float2bfloat16(ko - __bfloat162float(kh));
    g_vh[hto] = vh;
    g_vl[hto] = __float2bfloat16(vv - __bfloat162float(vh));
}

// ---------------------------------------------------------------------------
// Flash attention with tensor cores (causal, online softmax),
// cp.async double-buffered K/V tiles, single barrier per k-tile.
// ---------------------------------------------------------------------------
#define VP 104
#define ARRF (64 * VP * 2)
#define STGF (4 * ARRF)
#define FSM_BYTES (2 * STGF)

__global__ __launch_bounds__(256, 1)
void flash_mma_kernel() {
    extern __shared__ __nv_bfloat16 fsm[];
    const uint32_t sBase = (uint32_t)__cvta_generic_to_shared(fsm);

    const int bh   = blockIdx.y;
    const int qt   = (int)gridDim.x - 1 - (int)blockIdx.x;
    const int tid  = threadIdx.x;
    const int warp = tid >> 5;
    const int lane = tid & 31;
    const int g    = lane >> 2;
    const int t    = lane & 3;
    const int tile = lane >> 3;

    uint32_t qa_h[6][4], qa_l[6][4];
    {
        const size_t q0 = (size_t)(bh * T_ + qt * 128 + warp * 16) * D_;
        #pragma unroll
        for (int s = 0; s < 6; s++) {
            const int k0 = 16 * s + 2 * t;
            qa_h[s][0] = *(const uint32_t*)(g_qh + q0 + (size_t)g * D_ + k0);
            qa_h[s][1] = *(const uint32_t*)(g_qh + q0 + (size_t)(g + 8) * D_ + k0);
            qa_h[s][2] = *(const uint32_t*)(g_qh + q0 + (size_t)g * D_ + k0 + 8);
            qa_h[s][3] = *(const uint32_t*)(g_qh + q0 + (size_t)(g + 8) * D_ + k0 + 8);
            qa_l[s][0] = *(const uint32_t*)(g_ql + q0 + (size_t)g * D_ + k0);
            qa_l[s][1] = *(const uint32_t*)(g_ql + q0 + (size_t)(g + 8) * D_ + k0);
            qa_l[s][2] = *(const uint32_t*)(g_ql + q0 + (size_t)g * D_ + k0 + 8);
            qa_l[s][3] = *(const uint32_t*)(g_ql + q0 + (size_t)(g + 8) * D_ + k0 + 8);
        }
    }

    float o[12][4];
    #pragma unroll
    for (int i = 0; i < 12; i++)
        #pragma unroll
        for (int r = 0; r < 4; r++) o[i][r] = 0.f;
    float m0 = -1e30f, m1 = -1e30f, l0 = 0.f, l1 = 0.f;

    const int r0g   = qt * 128 + warp * 16 + g;
    const int r1g   = r0g + 8;
    const int rmaxw = qt * 128 + warp * 16 + 15;
    const int nkb   = 2 * qt + 2;

    const __nv_bfloat16* gkh = g_kh + (size_t)bh * T_ * D_;
    const __nv_bfloat16* gkl = g_kl + (size_t)bh * T_ * D_;
    const __nv_bfloat16* gvh = g_vh + (size_t)bh * T_ * D_;
    const __nv_bfloat16* gvl = g_vl + (size_t)bh * T_ * D_;

    auto issue_load = [&](int kb) {
        const size_t src = (size_t)(kb * 64) * D_;
        const uint32_t sb = sBase + (uint32_t)(kb & 1) * STGF;
        #pragma unroll
        for (int i = tid; i < 768; i += 256) {
            const int row = i / 12;
            const int ch  = (i % 12) * 8;
            const size_t go = src + (size_t)row * D_ + ch;
            const uint32_t so = (uint32_t)(row * VP + ch) * 2;
            CP16(sb + so,            gkh + go);
            CP16(sb + ARRF + so,     gkl + go);
            CP16(sb + 2 * ARRF + so, gvh + go);
            CP16(sb + 3 * ARRF + so, gvl + go);
        }
        CP_COMMIT();
    };

    issue_load(0);

    for (int kb = 0; kb < nkb; kb++) {
        CP_WAIT(0);          // stage kb landed
        __syncthreads();     // all threads finished reading stage kb-1
        if (kb + 1 < nkb) issue_load(kb + 1);  // other buffer; overlaps compute

        const uint32_t stg = sBase + (uint32_t)(kb & 1) * STGF;

        if (kb * 64 <= rmaxw) {
            float sacc[8][4];
            #pragma unroll
            for (int i = 0; i < 8; i++)
                #pragma unroll
                for (int r = 0; r < 4; r++) sacc[i][r] = 0.f;

            #pragma unroll
            for (int s = 0; s < 6; s++) {
                #pragma unroll
                for (int p = 0; p < 4; p++) {
                    const uint32_t addr = stg +
                        (uint32_t)(((p * 16 + (tile >> 1) * 8 + (lane & 7)) * VP +
                                    s * 16 + (tile & 1) * 8) * 2);
                    uint32_t bh4[4], bl4[4];
                    LDSM_X4(bh4, addr);
                    LDSM_X4(bl4, addr + ARRF);
                    MMA_BF16(sacc[2 * p],     qa_h[s], bh4);
                    MMA_BF16(sacc[2 * p + 1], qa_h[s], bh4 + 2);
                    MMA_BF16(sacc[2 * p],     qa_h[s], bl4);
                    MMA_BF16(sacc[2 * p + 1], qa_h[s], bl4 + 2);
                    MMA_BF16(sacc[2 * p],     qa_l[s], bh4);
                    MMA_BF16(sacc[2 * p + 1], qa_l[s], bh4 + 2);
                }
            }

            if (kb * 64 + 63 > qt * 128 + warp * 16) {
                #pragma unroll
                for (int nt = 0; nt < 8; nt++) {
                    const int c = kb * 64 + nt * 8 + 2 * t;
                    if (c     > r0g) sacc[nt][0] = -1e30f;
                    if (c + 1 > r0g) sacc[nt][1] = -1e30f;
                    if (c     > r1g) sacc[nt][2] = -1e30f;
                    if (c + 1 > r1g) sacc[nt][3] = -1e30f;
                }
            }

            float tm0 = -1e30f, tm1 = -1e30f;
            #pragma unroll
            for (int nt = 0; nt < 8; nt++) {
                tm0 = fmaxf(tm0, fmaxf(sacc[nt][0], sacc[nt][1]));
                tm1 = fmaxf(tm1, fmaxf(sacc[nt][2], sacc[nt][3]));
            }
            tm0 = fmaxf(tm0, __shfl_xor_sync(0xffffffffu, tm0, 1));
            tm0 = fmaxf(tm0, __shfl_xor_sync(0xffffffffu, tm0, 2));
            tm1 = fmaxf(tm1, __shfl_xor_sync(0xffffffffu, tm1, 1));
            tm1 = fmaxf(tm1, __shfl_xor_sync(0xffffffffu, tm1, 2));
            const float mn0 = fmaxf(m0, tm0);
            const float mn1 = fmaxf(m1, tm1);
            const float a0 = __expf(m0 - mn0);
            const float a1 = __expf(m1 - mn1);
            l0 *= a0; l1 *= a1;
            #pragma unroll
            for (int i = 0; i < 12; i++) {
                o[i][0] *= a0; o[i][1] *= a0;
                o[i][2] *= a1; o[i][3] *= a1;
            }
            #pragma unroll
            for (int nt = 0; nt < 8; nt++) {
                const float p0 = __expf(sacc[nt][0] - mn0);
                const float p1 = __expf(sacc[nt][1] - mn0);
                const float p2 = __expf(sacc[nt][2] - mn1);
                const float p3 = __expf(sacc[nt][3] - mn1);
                l0 += p0 + p1;
                l1 += p2 + p3;
                sacc[nt][0] = p0; sacc[nt][1] = p1;
                sacc[nt][2] = p2; sacc[nt][3] = p3;
            }
            m0 = mn0; m1 = mn1;

            uint32_t pah[4][4], pal[4][4];
            #pragma unroll
            for (int s2 = 0; s2 < 4; s2++) {
                #pragma unroll
                for (int hh = 0; hh < 2; hh++) {
                    const float e0 = sacc[2 * s2 + hh][0];
                    const float e1 = sacc[2 * s2 + hh][1];
                    const float e2 = sacc[2 * s2 + hh][2];
                    const float e3 = sacc[2 * s2 + hh][3];
                    __nv_bfloat162 h01 = __floats2bfloat162_rn(e0, e1);
                    __nv_bfloat162 h23 = __floats2bfloat162_rn(e2, e3);
                    __nv_bfloat162 l01 = __floats2bfloat162_rn(
                        e0 - __bfloat162float(h01.x), e1 - __bfloat162float(h01.y));
                    __nv_bfloat162 l23 = __floats2bfloat162_rn(
                        e2 - __bfloat162float(h23.x), e3 - __bfloat162float(h23.y));
                    pah[s2][hh * 2 + 0] = *(uint32_t*)&h01;
                    pah[s2][hh * 2 + 1] = *(uint32_t*)&h23;
                    pal[s2][hh * 2 + 0] = *(uint32_t*)&l01;
                    pal[s2][hh * 2 + 1] = *(uint32_t*)&l23;
                }
            }

            #pragma unroll
            for (int dp = 0; dp < 6; dp++) {
                #pragma unroll
                for (int s2 = 0; s2 < 4; s2++) {
                    const uint32_t addr = stg + 2 * ARRF +
                        (uint32_t)(((s2 * 16 + (tile & 1) * 8 + (lane & 7)) * VP +
                                    dp * 16 + (tile >> 1) * 8) * 2);
                    uint32_t bv[4], bvl[4];
                    LDSM_X4_T(bv, addr);
                    LDSM_X4_T(bvl, addr + ARRF);
                    MMA_BF16(o[2 * dp],     pah[s2], bv);
                    MMA_BF16(o[2 * dp + 1], pah[s2], bv + 2);
                    MMA_BF16(o[2 * dp],     pah[s2], bvl);
                    MMA_BF16(o[2 * dp + 1], pah[s2], bvl + 2);
                    MMA_BF16(o[2 * dp],     pal[s2], bv);
                    MMA_BF16(o[2 * dp + 1], pal[s2], bv + 2);
                }
            }
        }
    }

    l0 += __shfl_xor_sync(0xffffffffu, l0, 1);
    l0 += __shfl_xor_sync(0xffffffffu, l0, 2);
    l1 += __shfl_xor_sync(0xffffffffu, l1, 1);
    l1 += __shfl_xor_sync(0xffffffffu, l1, 2);
    const float i0 = 1.f / l0;
    const float i1 = 1.f / l1;

    const int b = bh >> 4;
    const int h = bh & 15;
    #pragma unroll
    for (int nt = 0; nt < 12; nt++) {
        const int d = nt * 8 + 2 * t;
        const size_t off0 = (size_t)(b * T_ + r0g) * C_ + h * D_ + d;
        const size_t off1 = (size_t)(b * T_ + r1g) * C_ + h * D_ + d;
        const float v00 = o[nt][0] * i0, v01 = o[nt][1] * i0;
        const float v10 = o[nt][2] * i1, v11 = o[nt][3] * i1;
        __nv_bfloat162 h0 = __floats2bfloat162_rn(v00, v01);
        __nv_bfloat162 h1 = __floats2bfloat162_rn(v10, v11);
        __nv_bfloat162 lo0 = __floats2bfloat162_rn(
            v00 - __bfloat162float(h0.x), v01 - __bfloat162float(h0.y));
        __nv_bfloat162 lo1 = __floats2bfloat162_rn(
            v10 - __bfloat162float(h1.x), v11 - __bfloat162float(h1.y));
        *(__nv_bfloat162*)(g_ath + off0) = h0;
        *(__nv_bfloat162*)(g_atl + off0) = lo0;
        *(__nv_bfloat162*)(g_ath + off1) = h1;
        *(__nv_bfloat162*)(g_atl + off1) = lo1;
    }
}

// ---------------------------------------------------------------------------
// Launch
// ---------------------------------------------------------------------------
extern "C" void kernel_launch(void* const* d_in, const int* in_sizes, int n_in,
                              void* d_out, int out_size) {
    const float* x          = (const float*)d_in[0];
    const float* coords     = (const float*)d_in[1];
    const int*   token_type = (const int*)  d_in[2];
    const float* W_qkv      = (const float*)d_in[3];
    const float* W_out      = (const float*)d_in[4];
    const float* q_scale    = (const float*)d_in[5];
    const float* k_scale    = (const float*)d_in[6];
    float* out = (float*)d_out;

    void *p_qkv;
    void *p_xh, *p_xl, *p_wqh, *p_wql, *p_ath, *p_atl, *p_woh, *p_wol;
    cudaGetSymbolAddress(&p_qkv, g_qkv);
    cudaGetSymbolAddress(&p_xh,  g_xh);
    cudaGetSymbolAddress(&p_xl,  g_xl);
    cudaGetSymbolAddress(&p_wqh, g_wqh);
    cudaGetSymbolAddress(&p_wql, g_wql);
    cudaGetSymbolAddress(&p_ath, g_ath);
    cudaGetSymbolAddress(&p_atl, g_atl);
    cudaGetSymbolAddress(&p_woh, g_woh);
    cudaGetSymbolAddress(&p_wol, g_wol);

    cudaFuncSetAttribute(bmma_nt,
                         cudaFuncAttributeMaxDynamicSharedMemorySize, GSM_BYTES);
    cudaFuncSetAttribute(flash_mma_kernel,
                         cudaFuncAttributeMaxDynamicSharedMemorySize, FSM_BYTES);

    // 0) split x and W_qkv into bf16 hi/lo
    {
        int n = BT_ * C_;
        split_kernel<<<n / 4 / 256, 256>>>(x, (__nv_bfloat16*)p_xh, (__nv_bfloat16*)p_xl, n);
        n = C3_ * C_;
        split_kernel<<<n / 4 / 256, 256>>>(W_qkv, (__nv_bfloat16*)p_wqh, (__nv_bfloat16*)p_wql, n);
    }

    // 1) qkv = x @ W_qkv^T
    {
        dim3 grid(C3_ / 128, BT_ / 128);
        bmma_nt<<<grid, 256, GSM_BYTES>>>(
            (const __nv_bfloat16*)p_xh, (const __nv_bfloat16*)p_xl,
            (const __nv_bfloat16*)p_wqh, (const __nv_bfloat16*)p_wql,
            (float*)p_qkv, BT_, C3_, C_);
    }

    // 2) RMS-norm + RoPE + hi/lo split to head-major
    norm_rope_kernel<<<B_ * T_ * H_, 96>>>(coords, token_type, q_scale, k_scale);

    // 3) causal flash attention (tensor cores, cp.async pipeline)
    {
        dim3 grid(T_ / 128, BH_);
        flash_mma_kernel<<<grid, 256, FSM_BYTES>>>();
    }

    // 4) out = att @ W_out^T
    {
        int n = C_ * C_;
        split_kernel<<<n / 4 / 256, 256>>>(W_out, (__nv_bfloat16*)p_woh, (__nv_bfloat16*)p_wol, n);
        dim3 grid(C_ / 128, BT_ / 128);
        bmma_nt<<<grid, 256, GSM_BYTES>>>(
            (const __nv_bfloat16*)p_ath, (const __nv_bfloat16*)p_atl,
            (const __nv_bfloat16*)p_woh, (const __nv_bfloat16*)p_wol,
            out, BT_, C_, C_);
    }
}

// round 13
// speedup vs baseline: 1.0022x; 1.0022x over previous
#include <cuda_runtime.h>
#include <cuda_bf16.h>
#include <math.h>
#include <stdint.h>

// Problem constants
#define B_  2
#define T_  2048
#define C_  1536
#define H_  16
#define D_  96
#define C3_ (3 * C_)      // 4608
#define BT_ (B_ * T_)     // 4096
#define BH_ (B_ * H_)     // 32

// fp32 scratch
__device__ float g_qkv[(size_t)BT_ * C3_];

// bf16 hi/lo split scratch for GEMMs
__device__ __nv_bfloat16 g_xh [(size_t)BT_  * C_];
__device__ __nv_bfloat16 g_xl [(size_t)BT_  * C_];
__device__ __nv_bfloat16 g_wqh[(size_t)C3_  * C_];
__device__ __nv_bfloat16 g_wql[(size_t)C3_  * C_];
__device__ __nv_bfloat16 g_ath[(size_t)BT_  * C_];
__device__ __nv_bfloat16 g_atl[(size_t)BT_  * C_];
__device__ __nv_bfloat16 g_woh[(size_t)C_   * C_];
__device__ __nv_bfloat16 g_wol[(size_t)C_   * C_];

// bf16 hi/lo q/k/v for attention, layout [bh][t][d]
__device__ __nv_bfloat16 g_qh[(size_t)BH_ * T_ * D_];
__device__ __nv_bfloat16 g_ql[(size_t)BH_ * T_ * D_];
__device__ __nv_bfloat16 g_kh[(size_t)BH_ * T_ * D_];
__device__ __nv_bfloat16 g_kl[(size_t)BH_ * T_ * D_];
__device__ __nv_bfloat16 g_vh[(size_t)BH_ * T_ * D_];
__device__ __nv_bfloat16 g_vl[(size_t)BH_ * T_ * D_];

// ---------------------------------------------------------------------------
// helpers
// ---------------------------------------------------------------------------
#define MMA_BF16(d, a, b)                                                     \
    asm volatile(                                                             \
        "mma.sync.aligned.m16n8k16.row.col.f32.bf16.bf16.f32 "                \
        "{%0,%1,%2,%3}, {%4,%5,%6,%7}, {%8,%9}, {%0,%1,%2,%3};"               \
        : "+f"((d)[0]), "+f"((d)[1]), "+f"((d)[2]), "+f"((d)[3])              \
        : "r"((a)[0]), "r"((a)[1]), "r"((a)[2]), "r"((a)[3]),                 \
          "r"((b)[0]), "r"((b)[1]))

#define LDSM_X4(r, a)                                                         \
    asm volatile("ldmatrix.sync.aligned.m8n8.x4.shared.b16 {%0,%1,%2,%3}, [%4];" \
        : "=r"((r)[0]), "=r"((r)[1]), "=r"((r)[2]), "=r"((r)[3]) : "r"(a))

#define LDSM_X4_T(r, a)                                                       \
    asm volatile("ldmatrix.sync.aligned.m8n8.x4.trans.shared.b16 {%0,%1,%2,%3}, [%4];" \
        : "=r"((r)[0]), "=r"((r)[1]), "=r"((r)[2]), "=r"((r)[3]) : "r"(a))

#define CP16(dst, src)                                                        \
    asm volatile("cp.async.cg.shared.global [%0], [%1], 16;"                  \
        :: "r"(dst), "l"(src))
#define CP_COMMIT() asm volatile("cp.async.commit_group;")
#define CP_WAIT(n)  asm volatile("cp.async.wait_group %0;" :: "n"(n))

// ---------------------------------------------------------------------------
// fp32 -> (bf16 hi, bf16 lo) split.  n must be divisible by 4.
// ---------------------------------------------------------------------------
__global__ __launch_bounds__(256)
void split_kernel(const float* __restrict__ in,
                  __nv_bfloat16* __restrict__ hi,
                  __nv_bfloat16* __restrict__ lo, int n) {
    int i = (blockIdx.x * 256 + threadIdx.x) * 4;
    if (i >= n) return;
    float4 v = *reinterpret_cast<const float4*>(in + i);
    __nv_bfloat16 h0 = __float2bfloat16(v.x);
    __nv_bfloat16 h1 = __float2bfloat16(v.y);
    __nv_bfloat16 h2 = __float2bfloat16(v.z);
    __nv_bfloat16 h3 = __float2bfloat16(v.w);
    __nv_bfloat16 l0 = __float2bfloat16(v.x - __bfloat162float(h0));
    __nv_bfloat16 l1 = __float2bfloat16(v.y - __bfloat162float(h1));
    __nv_bfloat16 l2 = __float2bfloat16(v.z - __bfloat162float(h2));
    __nv_bfloat16 l3 = __float2bfloat16(v.w - __bfloat162float(h3));
    __nv_bfloat162* hp = reinterpret_cast<__nv_bfloat162*>(hi + i);
    __nv_bfloat162* lp = reinterpret_cast<__nv_bfloat162*>(lo + i);
    hp[0] = __nv_bfloat162(h0, h1);
    hp[1] = __nv_bfloat162(h2, h3);
    lp[0] = __nv_bfloat162(l0, l1);
    lp[1] = __nv_bfloat162(l2, l3);
}

// ---------------------------------------------------------------------------
// Tensor-core GEMM (NT) with bf16 hi/lo split, cp.async double buffer,
// ldmatrix operand fetch, k-tile 32, SA=40 (round-10 measured-best, exactly).
// ---------------------------------------------------------------------------
#define SA 40
#define ARR_B   (128 * SA * 2)
#define STAGE_B (4 * ARR_B)
#define GSM_BYTES (2 * STAGE_B)

__global__ __launch_bounds__(256)
void bmma_nt(const __nv_bfloat16* __restrict__ Ah,
             const __nv_bfloat16* __restrict__ Al,
             const __nv_bfloat16* __restrict__ Bh,
             const __nv_bfloat16* __restrict__ Bl,
             float* __restrict__ Cm, int M, int N, int K) {
    extern __shared__ __nv_bfloat16 gsm[];
    const uint32_t smemU = (uint32_t)__cvta_generic_to_shared(gsm);

    const int tid  = threadIdx.x;
    const int m0   = blockIdx.y * 128;
    const int n0   = blockIdx.x * 128;
    const int lr   = tid >> 1;
    const int lh   = tid & 1;
    const int warp = tid >> 5;
    const int lane = tid & 31;
    const int wm   = (warp & 1) * 64;
    const int wn   = (warp >> 1) * 32;
    const int g    = lane >> 2;
    const int t    = lane & 3;
    const int tile = lane >> 3;

    const __nv_bfloat16* aph = Ah + (size_t)(m0 + lr) * K + lh * 16;
    const __nv_bfloat16* apl = Al + (size_t)(m0 + lr) * K + lh * 16;
    const __nv_bfloat16* bph = Bh + (size_t)(n0 + lr) * K + lh * 16;
    const __nv_bfloat16* bpl = Bl + (size_t)(n0 + lr) * K + lh * 16;

    const uint32_t dOff = (uint32_t)(lr * SA + lh * 16) * 2;
    const uint32_t aByte = (uint32_t)((wm + (lane & 15)) * SA + (lane >> 4) * 8) * 2;
    const uint32_t bByte = (uint32_t)((wn + (tile >> 1) * 8 + (lane & 7)) * SA +
                                      (tile & 1) * 8) * 2;

    float acc[4][4][4];
    #pragma unroll
    for (int i = 0; i < 4; i++)
        #pragma unroll
        for (int j = 0; j < 4; j++)
            #pragma unroll
            for (int r = 0; r < 4; r++) acc[i][j][r] = 0.f;

    const int nkt = K / 32;

    auto issue_stage = [&](int kt) {
        const int ko = kt * 32;
        const uint32_t sb = smemU + (kt & 1) * STAGE_B + dOff;
        CP16(sb,                  aph + ko);
        CP16(sb + 16,             aph + ko + 8);
        CP16(sb + ARR_B,          apl + ko);
        CP16(sb + ARR_B + 16,     apl + ko + 8);
        CP16(sb + 2 * ARR_B,      bph + ko);
        CP16(sb + 2 * ARR_B + 16, bph + ko + 8);
        CP16(sb + 3 * ARR_B,      bpl + ko);
        CP16(sb + 3 * ARR_B + 16, bpl + ko + 8);
        CP_COMMIT();
    };

    issue_stage(0);

    for (int kt = 0; kt < nkt; kt++) {
        CP_WAIT(0);
        __syncthreads();
        if (kt + 1 < nkt) issue_stage(kt + 1);

        const uint32_t stage = smemU + (kt & 1) * STAGE_B;

        #pragma unroll
        for (int kk = 0; kk < 32; kk += 16) {
            uint32_t ah[4][4], al[4][4];
            #pragma unroll
            for (int mt = 0; mt < 4; mt++) {
                const uint32_t aa = stage + aByte + mt * (16 * SA * 2) + kk * 2;
                LDSM_X4(ah[mt], aa);
                LDSM_X4(al[mt], aa + ARR_B);
            }
            uint32_t bhf[2][4], blf[2][4];
            #pragma unroll
            for (int np = 0; np < 2; np++) {
                const uint32_t ba = stage + 2 * ARR_B + bByte + np * (16 * SA * 2) + kk * 2;
                LDSM_X4(bhf[np], ba);
                LDSM_X4(blf[np], ba + ARR_B);
            }
            #pragma unroll
            for (int mt = 0; mt < 4; mt++)
                #pragma unroll
                for (int nt = 0; nt < 4; nt++) {
                    const uint32_t* bhp = &bhf[nt >> 1][(nt & 1) * 2];
                    const uint32_t* blp = &blf[nt >> 1][(nt & 1) * 2];
                    MMA_BF16(acc[mt][nt], ah[mt], bhp);
                    MMA_BF16(acc[mt][nt], ah[mt], blp);
                    MMA_BF16(acc[mt][nt], al[mt], bhp);
                }
        }
    }

    #pragma unroll
    for (int mt = 0; mt < 4; mt++)
        #pragma unroll
        for (int nt = 0; nt < 4; nt++) {
            const int row = m0 + wm + mt * 16 + g;
            const int col = n0 + wn + nt * 8 + t * 2;
            float2 v01 = make_float2(acc[mt][nt][0], acc[mt][nt][1]);
            float2 v23 = make_float2(acc[mt][nt][2], acc[mt][nt][3]);
            *reinterpret_cast<float2*>(&Cm[(size_t)row * N + col])       = v01;
            *reinterpret_cast<float2*>(&Cm[(size_t)(row + 8) * N + col]) = v23;
        }
}

// ---------------------------------------------------------------------------
// QK RMS-norm + conditional 3D RoPE + transpose to [bh][t][d] as bf16 hi/lo.
// One block per (b,t,h), 96 threads.  __sincosf fast path.
// ---------------------------------------------------------------------------
__global__ __launch_bounds__(96)
void norm_rope_kernel(const float* __restrict__ coords,
                      const int*   __restrict__ token_type,
                      const float* __restrict__ q_scale,
                      const float* __restrict__ k_scale) {
    const int idx = blockIdx.x;
    const int h = idx & (H_ - 1);
    const int t = (idx >> 4) & (T_ - 1);
    const int b = idx >> 15;
    const int d = threadIdx.x;

    const size_t rowoff = (size_t)(b * T_ + t) * C3_;
    const float qv = g_qkv[rowoff +          h * D_ + d];
    const float kv = g_qkv[rowoff + C_     + h * D_ + d];
    const float vv = g_qkv[rowoff + 2 * C_ + h * D_ + d];

    __shared__ float red[8];
    float sq = qv * qv, sk = kv * kv;
    #pragma unroll
    for (int off = 16; off > 0; off >>= 1) {
        sq += __shfl_down_sync(0xffffffffu, sq, off);
        sk += __shfl_down_sync(0xffffffffu, sk, off);
    }
    const int w = d >> 5, lane = d & 31;
    if (lane == 0) { red[w] = sq; red[4 + w] = sk; }
    __syncthreads();
    const float ssq = red[0] + red[1] + red[2];
    const float ssk = red[4] + red[5] + red[6];

    const float qn = qv * rsqrtf(ssq * (1.0f / D_) + 1e-6f) * q_scale[d];
    const float kn = kv * rsqrtf(ssk * (1.0f / D_) + 1e-6f) * k_scale[d];

    __shared__ float shq[D_], shk[D_];
    shq[d] = qn;
    shk[d] = kn;
    const int tt = token_type[b * T_ + t];
    __syncthreads();

    float qo = qn, ko = kn;
    if (tt > 0) {
        const int a = d / 32;
        const int r = d - a * 32;
        const int j = (r < 16) ? r : r - 16;
        const float coord = coords[(size_t)(b * T_ + t) * 3 + a];
        const float inv_freq = __expf(-0.57564627324851142f * (float)j);
        const float ang = coord * inv_freq;
        float s, c;
        __sincosf(ang, &s, &c);
        if (r < 16) {
            qo = qn * c - shq[d + 16] * s;
            ko = kn * c - shk[d + 16] * s;
        } else {
            qo = shq[d - 16] * s + qn * c;
            ko = shk[d - 16] * s + kn * c;
        }
    }

    const size_t hto = ((size_t)(b * H_ + h) * T_ + t) * D_ + d;
    const float qs = qo * 0.10206207261596575f;
    __nv_bfloat16 qh = __float2bfloat16(qs);
    __nv_bfloat16 kh = __float2bfloat16(ko);
    __nv_bfloat16 vh = __float2bfloat16(vv);
    g_qh[hto] = qh;
    g_ql[hto] = __float2bfloat16(qs - __bfloat162float(qh));
    g_kh[hto] = kh;
    g_kl[hto] = __float2bfloat16(ko - __bfloat162float(kh));
    g_vh[hto] = vh;
    g_vl[hto] = __float2bfloat16(vv - __bfloat162float(vh));
}

// ---------------------------------------------------------------------------
// Flash attention with tensor cores (causal, online softmax).
// cp.async 3-stage ring, ISSUE-BEFORE-WAIT (round-6 order), two syncs/tile.
// ---------------------------------------------------------------------------
#define VP 104
#define ARRF (64 * VP * 2)
#define STGF (4 * ARRF)
#define NSTG 3
#define FSM_BYTES (NSTG * STGF)     // 159744

__global__ __launch_bounds__(256, 1)
void flash_mma_kernel() {
    extern __shared__ __nv_bfloat16 fsm[];
    const uint32_t sBase = (uint32_t)__cvta_generic_to_shared(fsm);

    const int bh   = blockIdx.y;
    const int qt   = (int)gridDim.x - 1 - (int)blockIdx.x;
    const int tid  = threadIdx.x;
    const int warp = tid >> 5;
    const int lane = tid & 31;
    const int g    = lane >> 2;
    const int t    = lane & 3;
    const int tile = lane >> 3;

    uint32_t qa_h[6][4], qa_l[6][4];
    {
        const size_t q0 = (size_t)(bh * T_ + qt * 128 + warp * 16) * D_;
        #pragma unroll
        for (int s = 0; s < 6; s++) {
            const int k0 = 16 * s + 2 * t;
            qa_h[s][0] = *(const uint32_t*)(g_qh + q0 + (size_t)g * D_ + k0);
            qa_h[s][1] = *(const uint32_t*)(g_qh + q0 + (size_t)(g + 8) * D_ + k0);
            qa_h[s][2] = *(const uint32_t*)(g_qh + q0 + (size_t)g * D_ + k0 + 8);
            qa_h[s][3] = *(const uint32_t*)(g_qh + q0 + (size_t)(g + 8) * D_ + k0 + 8);
            qa_l[s][0] = *(const uint32_t*)(g_ql + q0 + (size_t)g * D_ + k0);
            qa_l[s][1] = *(const uint32_t*)(g_ql + q0 + (size_t)(g + 8) * D_ + k0);
            qa_l[s][2] = *(const uint32_t*)(g_ql + q0 + (size_t)g * D_ + k0 + 8);
            qa_l[s][3] = *(const uint32_t*)(g_ql + q0 + (size_t)(g + 8) * D_ + k0 + 8);
        }
    }

    float o[12][4];
    #pragma unroll
    for (int i = 0; i < 12; i++)
        #pragma unroll
        for (int r = 0; r < 4; r++) o[i][r] = 0.f;
    float m0 = -1e30f, m1 = -1e30f, l0 = 0.f, l1 = 0.f;

    const int r0g   = qt * 128 + warp * 16 + g;
    const int r1g   = r0g + 8;
    const int rmaxw = qt * 128 + warp * 16 + 15;
    const int nkb   = 2 * qt + 2;

    const __nv_bfloat16* gkh = g_kh + (size_t)bh * T_ * D_;
    const __nv_bfloat16* gkl = g_kl + (size_t)bh * T_ * D_;
    const __nv_bfloat16* gvh = g_vh + (size_t)bh * T_ * D_;
    const __nv_bfloat16* gvl = g_vl + (size_t)bh * T_ * D_;

    auto issue_load = [&](int kb, int st) {
        const size_t src = (size_t)(kb * 64) * D_;
        const uint32_t sb = sBase + (uint32_t)st * STGF;
        #pragma unroll
        for (int i = tid; i < 768; i += 256) {
            const int row = i / 12;
            const int ch  = (i % 12) * 8;
            const size_t go = src + (size_t)row * D_ + ch;
            const uint32_t so = (uint32_t)(row * VP + ch) * 2;
            CP16(sb + so,            gkh + go);
            CP16(sb + ARRF + so,     gkl + go);
            CP16(sb + 2 * ARRF + so, gvh + go);
            CP16(sb + 3 * ARRF + so, gvl + go);
        }
        CP_COMMIT();
    };

    issue_load(0, 0);
    if (nkb > 1) issue_load(1, 1);

    int st2 = 2 % NSTG;   // stage slot for kb+2 issues, tracked incrementally
    int stc = 0;          // stage slot of current compute tile

    for (int kb = 0; kb < nkb; kb++) {
        // issue-before-wait: deepest prefetch first, then drain to stage kb
        if (kb + 2 < nkb) {
            issue_load(kb + 2, st2);
            if (++st2 == NSTG) st2 = 0;
            CP_WAIT(2);
        } else if (kb + 1 < nkb) {
            CP_WAIT(1);
        } else {
            CP_WAIT(0);
        }
        __syncthreads();

        const uint32_t stg = sBase + (uint32_t)stc * STGF;
        if (++stc == NSTG) stc = 0;

        if (kb * 64 <= rmaxw) {
            float sacc[8][4];
            #pragma unroll
            for (int i = 0; i < 8; i++)
                #pragma unroll
                for (int r = 0; r < 4; r++) sacc[i][r] = 0.f;

            #pragma unroll
            for (int s = 0; s < 6; s++) {
                #pragma unroll
                for (int p = 0; p < 4; p++) {
                    const uint32_t addr = stg +
                        (uint32_t)(((p * 16 + (tile >> 1) * 8 + (lane & 7)) * VP +
                                    s * 16 + (tile & 1) * 8) * 2);
                    uint32_t bh4[4], bl4[4];
                    LDSM_X4(bh4, addr);
                    LDSM_X4(bl4, addr + ARRF);
                    MMA_BF16(sacc[2 * p],     qa_h[s], bh4);
                    MMA_BF16(sacc[2 * p + 1], qa_h[s], bh4 + 2);
                    MMA_BF16(sacc[2 * p],     qa_h[s], bl4);
                    MMA_BF16(sacc[2 * p + 1], qa_h[s], bl4 + 2);
                    MMA_BF16(sacc[2 * p],     qa_l[s], bh4);
                    MMA_BF16(sacc[2 * p + 1], qa_l[s], bh4 + 2);
                }
            }

            if (kb * 64 + 63 > qt * 128 + warp * 16) {
                #pragma unroll
                for (int nt = 0; nt < 8; nt++) {
                    const int c = kb * 64 + nt * 8 + 2 * t;
                    if (c     > r0g) sacc[nt][0] = -1e30f;
                    if (c + 1 > r0g) sacc[nt][1] = -1e30f;
                    if (c     > r1g) sacc[nt][2] = -1e30f;
                    if (c + 1 > r1g) sacc[nt][3] = -1e30f;
                }
            }

            float tm0 = -1e30f, tm1 = -1e30f;
            #pragma unroll
            for (int nt = 0; nt < 8; nt++) {
                tm0 = fmaxf(tm0, fmaxf(sacc[nt][0], sacc[nt][1]));
                tm1 = fmaxf(tm1, fmaxf(sacc[nt][2], sacc[nt][3]));
            }
            tm0 = fmaxf(tm0, __shfl_xor_sync(0xffffffffu, tm0, 1));
            tm0 = fmaxf(tm0, __shfl_xor_sync(0xffffffffu, tm0, 2));
            tm1 = fmaxf(tm1, __shfl_xor_sync(0xffffffffu, tm1, 1));
            tm1 = fmaxf(tm1, __shfl_xor_sync(0xffffffffu, tm1, 2));
            const float mn0 = fmaxf(m0, tm0);
            const float mn1 = fmaxf(m1, tm1);
            const float a0 = __expf(m0 - mn0);
            const float a1 = __expf(m1 - mn1);
            l0 *= a0; l1 *= a1;
            #pragma unroll
            for (int i = 0; i < 12; i++) {
                o[i][0] *= a0; o[i][1] *= a0;
                o[i][2] *= a1; o[i][3] *= a1;
            }
            #pragma unroll
            for (int nt = 0; nt < 8; nt++) {
                const float p0 = __expf(sacc[nt][0] - mn0);
                const float p1 = __expf(sacc[nt][1] - mn0);
                const float p2 = __expf(sacc[nt][2] - mn1);
                const float p3 = __expf(sacc[nt][3] - mn1);
                l0 += p0 + p1;
                l1 += p2 + p3;
                sacc[nt][0] = p0; sacc[nt][1] = p1;
                sacc[nt][2] = p2; sacc[nt][3] = p3;
            }
            m0 = mn0; m1 = mn1;

            uint32_t pah[4][4], pal[4][4];
            #pragma unroll
            for (int s2 = 0; s2 < 4; s2++) {
                #pragma unroll
                for (int hh = 0; hh < 2; hh++) {
                    const float e0 = sacc[2 * s2 + hh][0];
                    const float e1 = sacc[2 * s2 + hh][1];
                    const float e2 = sacc[2 * s2 + hh][2];
                    const float e3 = sacc[2 * s2 + hh][3];
                    __nv_bfloat162 h01 = __floats2bfloat162_rn(e0, e1);
                    __nv_bfloat162 h23 = __floats2bfloat162_rn(e2, e3);
                    __nv_bfloat162 l01 = __floats2bfloat162_rn(
                        e0 - __bfloat162float(h01.x), e1 - __bfloat162float(h01.y));
                    __nv_bfloat162 l23 = __floats2bfloat162_rn(
                        e2 - __bfloat162float(h23.x), e3 - __bfloat162float(h23.y));
                    pah[s2][hh * 2 + 0] = *(uint32_t*)&h01;
                    pah[s2][hh * 2 + 1] = *(uint32_t*)&h23;
                    pal[s2][hh * 2 + 0] = *(uint32_t*)&l01;
                    pal[s2][hh * 2 + 1] = *(uint32_t*)&l23;
                }
            }

            #pragma unroll
            for (int dp = 0; dp < 6; dp++) {
                #pragma unroll
                for (int s2 = 0; s2 < 4; s2++) {
                    const uint32_t addr = stg + 2 * ARRF +
                        (uint32_t)(((s2 * 16 + (tile & 1) * 8 + (lane & 7)) * VP +
                                    dp * 16 + (tile >> 1) * 8) * 2);
                    uint32_t bv[4], bvl[4];
                    LDSM_X4_T(bv, addr);
                    LDSM_X4_T(bvl, addr + ARRF);
                    MMA_BF16(o[2 * dp],     pah[s2], bv);
                    MMA_BF16(o[2 * dp + 1], pah[s2], bv + 2);
                    MMA_BF16(o[2 * dp],     pah[s2], bvl);
                    MMA_BF16(o[2 * dp + 1], pah[s2], bvl + 2);
                    MMA_BF16(o[2 * dp],     pal[s2], bv);
                    MMA_BF16(o[2 * dp + 1], pal[s2], bv + 2);
                }
            }
        }
        __syncthreads();   // all reads of this stage done before it is re-filled
    }

    l0 += __shfl_xor_sync(0xffffffffu, l0, 1);
    l0 += __shfl_xor_sync(0xffffffffu, l0, 2);
    l1 += __shfl_xor_sync(0xffffffffu, l1, 1);
    l1 += __shfl_xor_sync(0xffffffffu, l1, 2);
    const float i0 = 1.f / l0;
    const float i1 = 1.f / l1;

    const int b = bh >> 4;
    const int h = bh & 15;
    #pragma unroll
    for (int nt = 0; nt < 12; nt++) {
        const int d = nt * 8 + 2 * t;
        const size_t off0 = (size_t)(b * T_ + r0g) * C_ + h * D_ + d;
        const size_t off1 = (size_t)(b * T_ + r1g) * C_ + h * D_ + d;
        const float v00 = o[nt][0] * i0, v01 = o[nt][1] * i0;
        const float v10 = o[nt][2] * i1, v11 = o[nt][3] * i1;
        __nv_bfloat162 h0 = __floats2bfloat162_rn(v00, v01);
        __nv_bfloat162 h1 = __floats2bfloat162_rn(v10, v11);
        __nv_bfloat162 lo0 = __floats2bfloat162_rn(
            v00 - __bfloat162float(h0.x), v01 - __bfloat162float(h0.y));
        __nv_bfloat162 lo1 = __floats2bfloat162_rn(
            v10 - __bfloat162float(h1.x), v11 - __bfloat162float(h1.y));
        *(__nv_bfloat162*)(g_ath + off0) = h0;
        *(__nv_bfloat162*)(g_atl + off0) = lo0;
        *(__nv_bfloat162*)(g_ath + off1) = h1;
        *(__nv_bfloat162*)(g_atl + off1) = lo1;
    }
}

// ---------------------------------------------------------------------------
// Launch
// ---------------------------------------------------------------------------
extern "C" void kernel_launch(void* const* d_in, const int* in_sizes, int n_in,
                              void* d_out, int out_size) {
    const float* x          = (const float*)d_in[0];
    const float* coords     = (const float*)d_in[1];
    const int*   token_type = (const int*)  d_in[2];
    const float* W_qkv      = (const float*)d_in[3];
    const float* W_out      = (const float*)d_in[4];
    const float* q_scale    = (const float*)d_in[5];
    const float* k_scale    = (const float*)d_in[6];
    float* out = (float*)d_out;

    void *p_qkv;
    void *p_xh, *p_xl, *p_wqh, *p_wql, *p_ath, *p_atl, *p_woh, *p_wol;
    cudaGetSymbolAddress(&p_qkv, g_qkv);
    cudaGetSymbolAddress(&p_xh,  g_xh);
    cudaGetSymbolAddress(&p_xl,  g_xl);
    cudaGetSymbolAddress(&p_wqh, g_wqh);
    cudaGetSymbolAddress(&p_wql, g_wql);
    cudaGetSymbolAddress(&p_ath, g_ath);
    cudaGetSymbolAddress(&p_atl, g_atl);
    cudaGetSymbolAddress(&p_woh, g_woh);
    cudaGetSymbolAddress(&p_wol, g_wol);

    cudaFuncSetAttribute(bmma_nt,
                         cudaFuncAttributeMaxDynamicSharedMemorySize, GSM_BYTES);
    cudaFuncSetAttribute(flash_mma_kernel,
                         cudaFuncAttributeMaxDynamicSharedMemorySize, FSM_BYTES);

    // 0) split x and W_qkv into bf16 hi/lo
    {
        int n = BT_ * C_;
        split_kernel<<<n / 4 / 256, 256>>>(x, (__nv_bfloat16*)p_xh, (__nv_bfloat16*)p_xl, n);
        n = C3_ * C_;
        split_kernel<<<n / 4 / 256, 256>>>(W_qkv, (__nv_bfloat16*)p_wqh, (__nv_bfloat16*)p_wql, n);
    }

    // 1) qkv = x @ W_qkv^T
    {
        dim3 grid(C3_ / 128, BT_ / 128);
        bmma_nt<<<grid, 256, GSM_BYTES>>>(
            (const __nv_bfloat16*)p_xh, (const __nv_bfloat16*)p_xl,
            (const __nv_bfloat16*)p_wqh, (const __nv_bfloat16*)p_wql,
            (float*)p_qkv, BT_, C3_, C_);
    }

    // 2) RMS-norm + RoPE + hi/lo split to head-major
    norm_rope_kernel<<<B_ * T_ * H_, 96>>>(coords, token_type, q_scale, k_scale);

    // 3) causal flash attention (tensor cores, 3-stage cp.async pipeline)
    {
        dim3 grid(T_ / 128, BH_);
        flash_mma_kernel<<<grid, 256, FSM_BYTES>>>();
    }

    // 4) out = att @ W_out^T
    {
        int n = C_ * C_;
        split_kernel<<<n / 4 / 256, 256>>>(W_out, (__nv_bfloat16*)p_woh, (__nv_bfloat16*)p_wol, n);
        dim3 grid(C_ / 128, BT_ / 128);
        bmma_nt<<<grid, 256, GSM_BYTES>>>(
            (const __nv_bfloat16*)p_ath, (const __nv_bfloat16*)p_atl,
            (const __nv_bfloat16*)p_woh, (const __nv_bfloat16*)p_wol,
            out, BT_, C_, C_);
    }
}

// round 15
// speedup vs baseline: 1.5402x; 1.5368x over previous
#include <cuda_runtime.h>
#include <cuda_bf16.h>
#include <math.h>
#include <stdint.h>

// Problem constants
#define B_  2
#define T_  2048
#define C_  1536
#define H_  16
#define D_  96
#define C3_ (3 * C_)      // 4608
#define BT_ (B_ * T_)     // 4096
#define BH_ (B_ * H_)     // 32

// fp32 scratch
__device__ float g_qkv[(size_t)BT_ * C3_];

// bf16 hi/lo split scratch for GEMMs
__device__ __nv_bfloat16 g_xh [(size_t)BT_  * C_];
__device__ __nv_bfloat16 g_xl [(size_t)BT_  * C_];
__device__ __nv_bfloat16 g_wqh[(size_t)C3_  * C_];
__device__ __nv_bfloat16 g_wql[(size_t)C3_  * C_];
__device__ __nv_bfloat16 g_ath[(size_t)BT_  * C_];
__device__ __nv_bfloat16 g_atl[(size_t)BT_  * C_];
__device__ __nv_bfloat16 g_woh[(size_t)C_   * C_];
__device__ __nv_bfloat16 g_wol[(size_t)C_   * C_];

// bf16 hi/lo q/k/v for attention, layout [bh][t][d]
__device__ __nv_bfloat16 g_qh[(size_t)BH_ * T_ * D_];
__device__ __nv_bfloat16 g_ql[(size_t)BH_ * T_ * D_];
__device__ __nv_bfloat16 g_kh[(size_t)BH_ * T_ * D_];
__device__ __nv_bfloat16 g_kl[(size_t)BH_ * T_ * D_];
__device__ __nv_bfloat16 g_vh[(size_t)BH_ * T_ * D_];
__device__ __nv_bfloat16 g_vl[(size_t)BH_ * T_ * D_];

// ---------------------------------------------------------------------------
// helpers
// ---------------------------------------------------------------------------
#define MMA_BF16(d, a, b)                                                     \
    asm volatile(                                                             \
        "mma.sync.aligned.m16n8k16.row.col.f32.bf16.bf16.f32 "                \
        "{%0,%1,%2,%3}, {%4,%5,%6,%7}, {%8,%9}, {%0,%1,%2,%3};"               \
        : "+f"((d)[0]), "+f"((d)[1]), "+f"((d)[2]), "+f"((d)[3])              \
        : "r"((a)[0]), "r"((a)[1]), "r"((a)[2]), "r"((a)[3]),                 \
          "r"((b)[0]), "r"((b)[1]))

#define LDSM_X4(r, a)                                                         \
    asm volatile("ldmatrix.sync.aligned.m8n8.x4.shared.b16 {%0,%1,%2,%3}, [%4];" \
        : "=r"((r)[0]), "=r"((r)[1]), "=r"((r)[2]), "=r"((r)[3]) : "r"(a))

#define LDSM_X4_T(r, a)                                                       \
    asm volatile("ldmatrix.sync.aligned.m8n8.x4.trans.shared.b16 {%0,%1,%2,%3}, [%4];" \
        : "=r"((r)[0]), "=r"((r)[1]), "=r"((r)[2]), "=r"((r)[3]) : "r"(a))

#define CP16(dst, src)                                                        \
    asm volatile("cp.async.cg.shared.global [%0], [%1], 16;"                  \
        :: "r"(dst), "l"(src))
#define CP_COMMIT() asm volatile("cp.async.commit_group;")
#define CP_WAIT(n)  asm volatile("cp.async.wait_group %0;" :: "n"(n))

// ---------------------------------------------------------------------------
// fp32 -> (bf16 hi, bf16 lo) split over TWO arrays in one launch.
// Indices [0, n1) come from in1 -> hi1/lo1; [n1, n1+n2) from in2 -> hi2/lo2.
// All sizes divisible by 4.
// ---------------------------------------------------------------------------
__global__ __launch_bounds__(256)
void split2_kernel(const float* __restrict__ in1,
                   __nv_bfloat16* __restrict__ hi1,
                   __nv_bfloat16* __restrict__ lo1, int n1,
                   const float* __restrict__ in2,
                   __nv_bfloat16* __restrict__ hi2,
                   __nv_bfloat16* __restrict__ lo2, int n2) {
    int i = (blockIdx.x * 256 + threadIdx.x) * 4;
    const float* in;
    __nv_bfloat16 *hi, *lo;
    if (i < n1) {
        in = in1; hi = hi1; lo = lo1;
    } else {
        i -= n1;
        if (i >= n2) return;
        in = in2; hi = hi2; lo = lo2;
    }
    float4 v = *reinterpret_cast<const float4*>(in + i);
    __nv_bfloat16 h0 = __float2bfloat16(v.x);
    __nv_bfloat16 h1 = __float2bfloat16(v.y);
    __nv_bfloat16 h2 = __float2bfloat16(v.z);
    __nv_bfloat16 h3 = __float2bfloat16(v.w);
    __nv_bfloat16 l0 = __float2bfloat16(v.x - __bfloat162float(h0));
    __nv_bfloat16 l1 = __float2bfloat16(v.y - __bfloat162float(h1));
    __nv_bfloat16 l2 = __float2bfloat16(v.z - __bfloat162float(h2));
    __nv_bfloat16 l3 = __float2bfloat16(v.w - __bfloat162float(h3));
    __nv_bfloat162* hp = reinterpret_cast<__nv_bfloat162*>(hi + i);
    __nv_bfloat162* lp = reinterpret_cast<__nv_bfloat162*>(lo + i);
    hp[0] = __nv_bfloat162(h0, h1);
    hp[1] = __nv_bfloat162(h2, h3);
    lp[0] = __nv_bfloat162(l0, l1);
    lp[1] = __nv_bfloat162(l2, l3);
}

__global__ __launch_bounds__(256)
void split_kernel(const float* __restrict__ in,
                  __nv_bfloat16* __restrict__ hi,
                  __nv_bfloat16* __restrict__ lo, int n) {
    int i = (blockIdx.x * 256 + threadIdx.x) * 4;
    if (i >= n) return;
    float4 v = *reinterpret_cast<const float4*>(in + i);
    __nv_bfloat16 h0 = __float2bfloat16(v.x);
    __nv_bfloat16 h1 = __float2bfloat16(v.y);
    __nv_bfloat16 h2 = __float2bfloat16(v.z);
    __nv_bfloat16 h3 = __float2bfloat16(v.w);
    __nv_bfloat16 l0 = __float2bfloat16(v.x - __bfloat162float(h0));
    __nv_bfloat16 l1 = __float2bfloat16(v.y - __bfloat162float(h1));
    __nv_bfloat16 l2 = __float2bfloat16(v.z - __bfloat162float(h2));
    __nv_bfloat16 l3 = __float2bfloat16(v.w - __bfloat162float(h3));
    __nv_bfloat162* hp = reinterpret_cast<__nv_bfloat162*>(hi + i);
    __nv_bfloat162* lp = reinterpret_cast<__nv_bfloat162*>(lo + i);
    hp[0] = __nv_bfloat162(h0, h1);
    hp[1] = __nv_bfloat162(h2, h3);
    lp[0] = __nv_bfloat162(l0, l1);
    lp[1] = __nv_bfloat162(l2, l3);
}

// ---------------------------------------------------------------------------
// Tensor-core GEMM (NT) with bf16 hi/lo split, cp.async double buffer,
// ldmatrix operand fetch, k-tile 32, SA=40 (round-10 measured-best, exactly).
// ---------------------------------------------------------------------------
#define SA 40
#define ARR_B   (128 * SA * 2)
#define STAGE_B (4 * ARR_B)
#define GSM_BYTES (2 * STAGE_B)

__global__ __launch_bounds__(256)
void bmma_nt(const __nv_bfloat16* __restrict__ Ah,
             const __nv_bfloat16* __restrict__ Al,
             const __nv_bfloat16* __restrict__ Bh,
             const __nv_bfloat16* __restrict__ Bl,
             float* __restrict__ Cm, int M, int N, int K) {
    extern __shared__ __nv_bfloat16 gsm[];
    const uint32_t smemU = (uint32_t)__cvta_generic_to_shared(gsm);

    const int tid  = threadIdx.x;
    const int m0   = blockIdx.y * 128;
    const int n0   = blockIdx.x * 128;
    const int lr   = tid >> 1;
    const int lh   = tid & 1;
    const int warp = tid >> 5;
    const int lane = tid & 31;
    const int wm   = (warp & 1) * 64;
    const int wn   = (warp >> 1) * 32;
    const int g    = lane >> 2;
    const int t    = lane & 3;
    const int tile = lane >> 3;

    const __nv_bfloat16* aph = Ah + (size_t)(m0 + lr) * K + lh * 16;
    const __nv_bfloat16* apl = Al + (size_t)(m0 + lr) * K + lh * 16;
    const __nv_bfloat16* bph = Bh + (size_t)(n0 + lr) * K + lh * 16;
    const __nv_bfloat16* bpl = Bl + (size_t)(n0 + lr) * K + lh * 16;

    const uint32_t dOff = (uint32_t)(lr * SA + lh * 16) * 2;
    const uint32_t aByte = (uint32_t)((wm + (lane & 15)) * SA + (lane >> 4) * 8) * 2;
    const uint32_t bByte = (uint32_t)((wn + (tile >> 1) * 8 + (lane & 7)) * SA +
                                      (tile & 1) * 8) * 2;

    float acc[4][4][4];
    #pragma unroll
    for (int i = 0; i < 4; i++)
        #pragma unroll
        for (int j = 0; j < 4; j++)
            #pragma unroll
            for (int r = 0; r < 4; r++) acc[i][j][r] = 0.f;

    const int nkt = K / 32;

    auto issue_stage = [&](int kt) {
        const int ko = kt * 32;
        const uint32_t sb = smemU + (kt & 1) * STAGE_B + dOff;
        CP16(sb,                  aph + ko);
        CP16(sb + 16,             aph + ko + 8);
        CP16(sb + ARR_B,          apl + ko);
        CP16(sb + ARR_B + 16,     apl + ko + 8);
        CP16(sb + 2 * ARR_B,      bph + ko);
        CP16(sb + 2 * ARR_B + 16, bph + ko + 8);
        CP16(sb + 3 * ARR_B,      bpl + ko);
        CP16(sb + 3 * ARR_B + 16, bpl + ko + 8);
        CP_COMMIT();
    };

    issue_stage(0);

    for (int kt = 0; kt < nkt; kt++) {
        CP_WAIT(0);
        __syncthreads();
        if (kt + 1 < nkt) issue_stage(kt + 1);

        const uint32_t stage = smemU + (kt & 1) * STAGE_B;

        #pragma unroll
        for (int kk = 0; kk < 32; kk += 16) {
            uint32_t ah[4][4], al[4][4];
            #pragma unroll
            for (int mt = 0; mt < 4; mt++) {
                const uint32_t aa = stage + aByte + mt * (16 * SA * 2) + kk * 2;
                LDSM_X4(ah[mt], aa);
                LDSM_X4(al[mt], aa + ARR_B);
            }
            uint32_t bhf[2][4], blf[2][4];
            #pragma unroll
            for (int np = 0; np < 2; np++) {
                const uint32_t ba = stage + 2 * ARR_B + bByte + np * (16 * SA * 2) + kk * 2;
                LDSM_X4(bhf[np], ba);
                LDSM_X4(blf[np], ba + ARR_B);
            }
            #pragma unroll
            for (int mt = 0; mt < 4; mt++)
                #pragma unroll
                for (int nt = 0; nt < 4; nt++) {
                    const uint32_t* bhp = &bhf[nt >> 1][(nt & 1) * 2];
                    const uint32_t* blp = &blf[nt >> 1][(nt & 1) * 2];
                    MMA_BF16(acc[mt][nt], ah[mt], bhp);
                    MMA_BF16(acc[mt][nt], ah[mt], blp);
                    MMA_BF16(acc[mt][nt], al[mt], bhp);
                }
        }
    }

    #pragma unroll
    for (int mt = 0; mt < 4; mt++)
        #pragma unroll
        for (int nt = 0; nt < 4; nt++) {
            const int row = m0 + wm + mt * 16 + g;
            const int col = n0 + wn + nt * 8 + t * 2;
            float2 v01 = make_float2(acc[mt][nt][0], acc[mt][nt][1]);
            float2 v23 = make_float2(acc[mt][nt][2], acc[mt][nt][3]);
            *reinterpret_cast<float2*>(&Cm[(size_t)row * N + col])       = v01;
            *reinterpret_cast<float2*>(&Cm[(size_t)(row + 8) * N + col]) = v23;
        }
}

// ---------------------------------------------------------------------------
// QK RMS-norm + conditional 3D RoPE + transpose to [bh][t][d] as bf16 hi/lo.
// One block per (b,t,h), 96 threads.  __sincosf fast path.
// ---------------------------------------------------------------------------
__global__ __launch_bounds__(96)
void norm_rope_kernel(const float* __restrict__ coords,
                      const int*   __restrict__ token_type,
                      const float* __restrict__ q_scale,
                      const float* __restrict__ k_scale) {
    const int idx = blockIdx.x;
    const int h = idx & (H_ - 1);
    const int t = (idx >> 4) & (T_ - 1);
    const int b = idx >> 15;
    const int d = threadIdx.x;

    const size_t rowoff = (size_t)(b * T_ + t) * C3_;
    const float qv = g_qkv[rowoff +          h * D_ + d];
    const float kv = g_qkv[rowoff + C_     + h * D_ + d];
    const float vv = g_qkv[rowoff + 2 * C_ + h * D_ + d];

    __shared__ float red[8];
    float sq = qv * qv, sk = kv * kv;
    #pragma unroll
    for (int off = 16; off > 0; off >>= 1) {
        sq += __shfl_down_sync(0xffffffffu, sq, off);
        sk += __shfl_down_sync(0xffffffffu, sk, off);
    }
    const int w = d >> 5, lane = d & 31;
    if (lane == 0) { red[w] = sq; red[4 + w] = sk; }
    __syncthreads();
    const float ssq = red[0] + red[1] + red[2];
    const float ssk = red[4] + red[5] + red[6];

    const float qn = qv * rsqrtf(ssq * (1.0f / D_) + 1e-6f) * q_scale[d];
    const float kn = kv * rsqrtf(ssk * (1.0f / D_) + 1e-6f) * k_scale[d];

    __shared__ float shq[D_], shk[D_];
    shq[d] = qn;
    shk[d] = kn;
    const int tt = token_type[b * T_ + t];
    __syncthreads();

    float qo = qn, ko = kn;
    if (tt > 0) {
        const int a = d / 32;
        const int r = d - a * 32;
        const int j = (r < 16) ? r : r - 16;
        const float coord = coords[(size_t)(b * T_ + t) * 3 + a];
        const float inv_freq = __expf(-0.57564627324851142f * (float)j);
        const float ang = coord * inv_freq;
        float s, c;
        __sincosf(ang, &s, &c);
        if (r < 16) {
            qo = qn * c - shq[d + 16] * s;
            ko = kn * c - shk[d + 16] * s;
        } else {
            qo = shq[d - 16] * s + qn * c;
            ko = shk[d - 16] * s + kn * c;
        }
    }

    const size_t hto = ((size_t)(b * H_ + h) * T_ + t) * D_ + d;
    const float qs = qo * 0.10206207261596575f;
    __nv_bfloat16 qh = __float2bfloat16(qs);
    __nv_bfloat16 kh = __float2bfloat16(ko);
    __nv_bfloat16 vh = __float2bfloat16(vv);
    g_qh[hto] = qh;
    g_ql[hto] = __float2bfloat16(qs - __bfloat162float(qh));
    g_kh[hto] = kh;
    g_kl[hto] = __float2bfloat16(ko - __bfloat162float(kh));
    g_vh[hto] = vh;
    g_vl[hto] = __float2bfloat16(vv - __bfloat162float(vh));
}

// ---------------------------------------------------------------------------
// Flash attention with tensor cores (causal, online softmax),
// cp.async double-buffered K/V tiles.  Round-10 measured-best config exactly:
// issue-before-wait, two syncs per k-tile, 2 stages, (256,1).
// ---------------------------------------------------------------------------
#define VP 104
#define ARRF (64 * VP * 2)
#define STGF (4 * ARRF)
#define FSM_BYTES (2 * STGF)

__global__ __launch_bounds__(256, 1)
void flash_mma_kernel() {
    extern __shared__ __nv_bfloat16 fsm[];
    const uint32_t sBase = (uint32_t)__cvta_generic_to_shared(fsm);

    const int bh   = blockIdx.y;
    const int qt   = (int)gridDim.x - 1 - (int)blockIdx.x;
    const int tid  = threadIdx.x;
    const int warp = tid >> 5;
    const int lane = tid & 31;
    const int g    = lane >> 2;
    const int t    = lane & 3;
    const int tile = lane >> 3;

    uint32_t qa_h[6][4], qa_l[6][4];
    {
        const size_t q0 = (size_t)(bh * T_ + qt * 128 + warp * 16) * D_;
        #pragma unroll
        for (int s = 0; s < 6; s++) {
            const int k0 = 16 * s + 2 * t;
            qa_h[s][0] = *(const uint32_t*)(g_qh + q0 + (size_t)g * D_ + k0);
            qa_h[s][1] = *(const uint32_t*)(g_qh + q0 + (size_t)(g + 8) * D_ + k0);
            qa_h[s][2] = *(const uint32_t*)(g_qh + q0 + (size_t)g * D_ + k0 + 8);
            qa_h[s][3] = *(const uint32_t*)(g_qh + q0 + (size_t)(g + 8) * D_ + k0 + 8);
            qa_l[s][0] = *(const uint32_t*)(g_ql + q0 + (size_t)g * D_ + k0);
            qa_l[s][1] = *(const uint32_t*)(g_ql + q0 + (size_t)(g + 8) * D_ + k0);
            qa_l[s][2] = *(const uint32_t*)(g_ql + q0 + (size_t)g * D_ + k0 + 8);
            qa_l[s][3] = *(const uint32_t*)(g_ql + q0 + (size_t)(g + 8) * D_ + k0 + 8);
        }
    }

    float o[12][4];
    #pragma unroll
    for (int i = 0; i < 12; i++)
        #pragma unroll
        for (int r = 0; r < 4; r++) o[i][r] = 0.f;
    float m0 = -1e30f, m1 = -1e30f, l0 = 0.f, l1 = 0.f;

    const int r0g   = qt * 128 + warp * 16 + g;
    const int r1g   = r0g + 8;
    const int rmaxw = qt * 128 + warp * 16 + 15;
    const int nkb   = 2 * qt + 2;

    const __nv_bfloat16* gkh = g_kh + (size_t)bh * T_ * D_;
    const __nv_bfloat16* gkl = g_kl + (size_t)bh * T_ * D_;
    const __nv_bfloat16* gvh = g_vh + (size_t)bh * T_ * D_;
    const __nv_bfloat16* gvl = g_vl + (size_t)bh * T_ * D_;

    auto issue_load = [&](int kb, int st) {
        const size_t src = (size_t)(kb * 64) * D_;
        const uint32_t sb = sBase + (uint32_t)st * STGF;
        #pragma unroll
        for (int i = tid; i < 768; i += 256) {
            const int row = i / 12;
            const int ch  = (i % 12) * 8;
            const size_t go = src + (size_t)row * D_ + ch;
            const uint32_t so = (uint32_t)(row * VP + ch) * 2;
            CP16(sb + so,            gkh + go);
            CP16(sb + ARRF + so,     gkl + go);
            CP16(sb + 2 * ARRF + so, gvh + go);
            CP16(sb + 3 * ARRF + so, gvl + go);
        }
        CP_COMMIT();
    };

    issue_load(0, 0);

    for (int kb = 0; kb < nkb; kb++) {
        if (kb + 1 < nkb) {
            issue_load(kb + 1, (kb + 1) & 1);
            CP_WAIT(1);
        } else {
            CP_WAIT(0);
        }
        __syncthreads();

        const uint32_t stg = sBase + (uint32_t)(kb & 1) * STGF;

        if (kb * 64 <= rmaxw) {
            float sacc[8][4];
            #pragma unroll
            for (int i = 0; i < 8; i++)
                #pragma unroll
                for (int r = 0; r < 4; r++) sacc[i][r] = 0.f;

            #pragma unroll
            for (int s = 0; s < 6; s++) {
                #pragma unroll
                for (int p = 0; p < 4; p++) {
                    const uint32_t addr = stg +
                        (uint32_t)(((p * 16 + (tile >> 1) * 8 + (lane & 7)) * VP +
                                    s * 16 + (tile & 1) * 8) * 2);
                    uint32_t bh4[4], bl4[4];
                    LDSM_X4(bh4, addr);
                    LDSM_X4(bl4, addr + ARRF);
                    MMA_BF16(sacc[2 * p],     qa_h[s], bh4);
                    MMA_BF16(sacc[2 * p + 1], qa_h[s], bh4 + 2);
                    MMA_BF16(sacc[2 * p],     qa_h[s], bl4);
                    MMA_BF16(sacc[2 * p + 1], qa_h[s], bl4 + 2);
                    MMA_BF16(sacc[2 * p],     qa_l[s], bh4);
                    MMA_BF16(sacc[2 * p + 1], qa_l[s], bh4 + 2);
                }
            }

            if (kb * 64 + 63 > qt * 128 + warp * 16) {
                #pragma unroll
                for (int nt = 0; nt < 8; nt++) {
                    const int c = kb * 64 + nt * 8 + 2 * t;
                    if (c     > r0g) sacc[nt][0] = -1e30f;
                    if (c + 1 > r0g) sacc[nt][1] = -1e30f;
                    if (c     > r1g) sacc[nt][2] = -1e30f;
                    if (c + 1 > r1g) sacc[nt][3] = -1e30f;
                }
            }

            float tm0 = -1e30f, tm1 = -1e30f;
            #pragma unroll
            for (int nt = 0; nt < 8; nt++) {
                tm0 = fmaxf(tm0, fmaxf(sacc[nt][0], sacc[nt][1]));
                tm1 = fmaxf(tm1, fmaxf(sacc[nt][2], sacc[nt][3]));
            }
            tm0 = fmaxf(tm0, __shfl_xor_sync(0xffffffffu, tm0, 1));
            tm0 = fmaxf(tm0, __shfl_xor_sync(0xffffffffu, tm0, 2));
            tm1 = fmaxf(tm1, __shfl_xor_sync(0xffffffffu, tm1, 1));
            tm1 = fmaxf(tm1, __shfl_xor_sync(0xffffffffu, tm1, 2));
            const float mn0 = fmaxf(m0, tm0);
            const float mn1 = fmaxf(m1, tm1);
            const float a0 = __expf(m0 - mn0);
            const float a1 = __expf(m1 - mn1);
            l0 *= a0; l1 *= a1;
            #pragma unroll
            for (int i = 0; i < 12; i++) {
                o[i][0] *= a0; o[i][1] *= a0;
                o[i][2] *= a1; o[i][3] *= a1;
            }
            #pragma unroll
            for (int nt = 0; nt < 8; nt++) {
                const float p0 = __expf(sacc[nt][0] - mn0);
                const float p1 = __expf(sacc[nt][1] - mn0);
                const float p2 = __expf(sacc[nt][2] - mn1);
                const float p3 = __expf(sacc[nt][3] - mn1);
                l0 += p0 + p1;
                l1 += p2 + p3;
                sacc[nt][0] = p0; sacc[nt][1] = p1;
                sacc[nt][2] = p2; sacc[nt][3] = p3;
            }
            m0 = mn0; m1 = mn1;

            uint32_t pah[4][4], pal[4][4];
            #pragma unroll
            for (int s2 = 0; s2 < 4; s2++) {
                #pragma unroll
                for (int hh = 0; hh < 2; hh++) {
                    const float e0 = sacc[2 * s2 + hh][0];
                    const float e1 = sacc[2 * s2 + hh][1];
                    const float e2 = sacc[2 * s2 + hh][2];
                    const float e3 = sacc[2 * s2 + hh][3];
                    __nv_bfloat162 h01 = __floats2bfloat162_rn(e0, e1);
                    __nv_bfloat162 h23 = __floats2bfloat162_rn(e2, e3);
                    __nv_bfloat162 l01 = __floats2bfloat162_rn(
                        e0 - __bfloat162float(h01.x), e1 - __bfloat162float(h01.y));
                    __nv_bfloat162 l23 = __floats2bfloat162_rn(
                        e2 - __bfloat162float(h23.x), e3 - __bfloat162float(h23.y));
                    pah[s2][hh * 2 + 0] = *(uint32_t*)&h01;
                    pah[s2][hh * 2 + 1] = *(uint32_t*)&h23;
                    pal[s2][hh * 2 + 0] = *(uint32_t*)&l01;
                    pal[s2][hh * 2 + 1] = *(uint32_t*)&l23;
                }
            }

            #pragma unroll
            for (int dp = 0; dp < 6; dp++) {
                #pragma unroll
                for (int s2 = 0; s2 < 4; s2++) {
                    const uint32_t addr = stg + 2 * ARRF +
                        (uint32_t)(((s2 * 16 + (tile & 1) * 8 + (lane & 7)) * VP +
                                    dp * 16 + (tile >> 1) * 8) * 2);
                    uint32_t bv[4], bvl[4];
                    LDSM_X4_T(bv, addr);
                    LDSM_X4_T(bvl, addr + ARRF);
                    MMA_BF16(o[2 * dp],     pah[s2], bv);
                    MMA_BF16(o[2 * dp + 1], pah[s2], bv + 2);
                    MMA_BF16(o[2 * dp],     pah[s2], bvl);
                    MMA_BF16(o[2 * dp + 1], pah[s2], bvl + 2);
                    MMA_BF16(o[2 * dp],     pal[s2], bv);
                    MMA_BF16(o[2 * dp + 1], pal[s2], bv + 2);
                }
            }
        }
        __syncthreads();
    }

    l0 += __shfl_xor_sync(0xffffffffu, l0, 1);
    l0 += __shfl_xor_sync(0xffffffffu, l0, 2);
    l1 += __shfl_xor_sync(0xffffffffu, l1, 1);
    l1 += __shfl_xor_sync(0xffffffffu, l1, 2);
    const float i0 = 1.f / l0;
    const float i1 = 1.f / l1;

    const int b = bh >> 4;
    const int h = bh & 15;
    #pragma unroll
    for (int nt = 0; nt < 12; nt++) {
        const int d = nt * 8 + 2 * t;
        const size_t off0 = (size_t)(b * T_ + r0g) * C_ + h * D_ + d;
        const size_t off1 = (size_t)(b * T_ + r1g) * C_ + h * D_ + d;
        const float v00 = o[nt][0] * i0, v01 = o[nt][1] * i0;
        const float v10 = o[nt][2] * i1, v11 = o[nt][3] * i1;
        __nv_bfloat162 h0 = __floats2bfloat162_rn(v00, v01);
        __nv_bfloat162 h1 = __floats2bfloat162_rn(v10, v11);
        __nv_bfloat162 lo0 = __floats2bfloat162_rn(
            v00 - __bfloat162float(h0.x), v01 - __bfloat162float(h0.y));
        __nv_bfloat162 lo1 = __floats2bfloat162_rn(
            v10 - __bfloat162float(h1.x), v11 - __bfloat162float(h1.y));
        *(__nv_bfloat162*)(g_ath + off0) = h0;
        *(__nv_bfloat162*)(g_atl + off0) = lo0;
        *(__nv_bfloat162*)(g_ath + off1) = h1;
        *(__nv_bfloat162*)(g_atl + off1) = lo1;
    }
}

// ---------------------------------------------------------------------------
// Launch
// ---------------------------------------------------------------------------
extern "C" void kernel_launch(void* const* d_in, const int* in_sizes, int n_in,
                              void* d_out, int out_size) {
    const float* x          = (const float*)d_in[0];
    const float* coords     = (const float*)d_in[1];
    const int*   token_type = (const int*)  d_in[2];
    const float* W_qkv      = (const float*)d_in[3];
    const float* W_out      = (const float*)d_in[4];
    const float* q_scale    = (const float*)d_in[5];
    const float* k_scale    = (const float*)d_in[6];
    float* out = (float*)d_out;

    void *p_qkv;
    void *p_xh, *p_xl, *p_wqh, *p_wql, *p_ath, *p_atl, *p_woh, *p_wol;
    cudaGetSymbolAddress(&p_qkv, g_qkv);
    cudaGetSymbolAddress(&p_xh,  g_xh);
    cudaGetSymbolAddress(&p_xl,  g_xl);
    cudaGetSymbolAddress(&p_wqh, g_wqh);
    cudaGetSymbolAddress(&p_wql, g_wql);
    cudaGetSymbolAddress(&p_ath, g_ath);
    cudaGetSymbolAddress(&p_atl, g_atl);
    cudaGetSymbolAddress(&p_woh, g_woh);
    cudaGetSymbolAddress(&p_wol, g_wol);

    cudaFuncSetAttribute(bmma_nt,
                         cudaFuncAttributeMaxDynamicSharedMemorySize, GSM_BYTES);
    cudaFuncSetAttribute(flash_mma_kernel,
                         cudaFuncAttributeMaxDynamicSharedMemorySize, FSM_BYTES);

    // 0) split x and W_qkv into bf16 hi/lo (one fused launch)
    {
        const int n1 = BT_ * C_;        // 6291456
        const int n2 = C3_ * C_;        // 7077888
        const int blocks = (n1 + n2) / 4 / 256;
        split2_kernel<<<blocks, 256>>>(
            x, (__nv_bfloat16*)p_xh, (__nv_bfloat16*)p_xl, n1,
            W_qkv, (__nv_bfloat16*)p_wqh, (__nv_bfloat16*)p_wql, n2);
    }

    // 1) qkv = x @ W_qkv^T
    {
        dim3 grid(C3_ / 128, BT_ / 128);
        bmma_nt<<<grid, 256, GSM_BYTES>>>(
            (const __nv_bfloat16*)p_xh, (const __nv_bfloat16*)p_xl,
            (const __nv_bfloat16*)p_wqh, (const __nv_bfloat16*)p_wql,
            (float*)p_qkv, BT_, C3_, C_);
    }

    // 2) RMS-norm + RoPE + hi/lo split to head-major
    norm_rope_kernel<<<B_ * T_ * H_, 96>>>(coords, token_type, q_scale, k_scale);

    // 3) causal flash attention (tensor cores, cp.async pipeline)
    {
        dim3 grid(T_ / 128, BH_);
        flash_mma_kernel<<<grid, 256, FSM_BYTES>>>();
    }

    // 4) out = att @ W_out^T
    {
        int n = C_ * C_;
        split_kernel<<<n / 4 / 256, 256>>>(W_out, (__nv_bfloat16*)p_woh, (__nv_bfloat16*)p_wol, n);
        dim3 grid(C_ / 128, BT_ / 128);
        bmma_nt<<<grid, 256, GSM_BYTES>>>(
            (const __nv_bfloat16*)p_ath, (const __nv_bfloat16*)p_atl,
            (const __nv_bfloat16*)p_woh, (const __nv_bfloat16*)p_wol,
            out, BT_, C_, C_);
    }
}